// round 1
// baseline (speedup 1.0000x reference)
#include <cuda_runtime.h>
#include <math.h>

#define BATCH 64
#define WPOS  2048
#define NPOS  (BATCH * WPOS)      // 131072 positions
#define CH    64                  // channels per layer
#define MT    128                 // positions per block (kernel A)
#define NBLK_A (NPOS / MT)        // 1024
#define KC    256                 // K chunk for dense split-K
#define FLATK (WPOS * CH)         // 131072
#define GSPLIT (FLATK / KC)       // 512

// Scratch (device globals — no allocation allowed)
__device__ __align__(16) float g_h4[(size_t)NPOS * CH];        // 32 MB: layer-4 output, == flat[b][k]
__device__ __align__(16) float g_part[(size_t)GSPLIT * 64 * 64]; // 8 MB: split-K partials

__device__ __forceinline__ float hsig(float v) {
    return __saturatef(fmaf(v, 0.2f, 0.5f));
}
__device__ __forceinline__ float tanh_fast(float v) {
    // accurate to ~1e-7 rel; clamp avoids inf/inf
    float xc = fminf(fmaxf(v, -15.f), 15.f);
    float e = __expf(xc + xc);
    return __fdividef(e - 1.f, e + 1.f);
}

// ---------------------------------------------------------------------------
// Kernel A: fused 4x ConvLSTM layers (each is a 64->192 per-position matmul +
// gate activations; f gate is dead because c0 == 0, Wh is dead because h0 == 0).
// Block = 128 positions, 256 threads, thread tile = 8(m) x 4(c) x 3(gate).
// ---------------------------------------------------------------------------
__global__ void __launch_bounds__(256, 2) k_lstm4(
    const float* __restrict__ x,
    const float* __restrict__ W0, const float* __restrict__ B0,
    const float* __restrict__ W1, const float* __restrict__ B1,
    const float* __restrict__ W2, const float* __restrict__ B2,
    const float* __restrict__ W3, const float* __restrict__ B3)
{
    extern __shared__ float sm[];
    float* sh = sm;                  // h buffer [128][64] (in-place across layers)
    float* Ws = sm + MT * CH;        // weights  [64][192]  (gate-major: [k][gate*64+c])
    float* Bs = Ws + CH * 192;       // bias     [192]

    const int tid = threadIdx.x;
    const int tx = tid & 15, ty = tid >> 4;
    const int m0 = ty * 8, c0 = tx * 4;
    const size_t p0 = (size_t)blockIdx.x * MT;

    // load input tile (coalesced float4)
    {
        const float4* xin = (const float4*)(x + p0 * CH);
        float4* sh4 = (float4*)sh;
        #pragma unroll
        for (int i = 0; i < (MT * CH / 4) / 256; ++i)
            sh4[tid + i * 256] = xin[tid + i * 256];
    }

    const float* Wl[4] = {W0, W1, W2, W3};
    const float* Bl[4] = {B0, B1, B2, B3};

    #pragma unroll 1
    for (int l = 0; l < 4; ++l) {
        const float* W  = Wl[l];
        const float* Bb = Bl[l];
        // Load weight slice [64][256], keeping only i (0:64), g (128:192), o (192:256)
        for (int i = tid; i < CH * 64; i += 256) {   // float4-indexed
            int k  = i >> 6;
            int nq = (i & 63) << 2;                  // global col base (mult of 4)
            float4 v = ((const float4*)W)[i];
            if (nq < 64)        *(float4*)&Ws[k * 192 + nq]      = v;  // i gate
            else if (nq >= 128) *(float4*)&Ws[k * 192 + nq - 64] = v;  // g, o gates
        }
        if (tid < 192) {
            int gate = tid >> 6, c = tid & 63;
            int gn = (gate == 0) ? c : (gate == 1 ? 128 + c : 192 + c);
            Bs[tid] = Bb[gn];
        }
        __syncthreads();

        float acc[3][4][8];
        #pragma unroll
        for (int g = 0; g < 3; ++g)
            #pragma unroll
            for (int j = 0; j < 4; ++j)
                #pragma unroll
                for (int i = 0; i < 8; ++i) acc[g][j][i] = 0.f;

        #pragma unroll 1
        for (int k = 0; k < CH; ++k) {
            float a[8];
            #pragma unroll
            for (int i = 0; i < 8; ++i) a[i] = sh[(m0 + i) * CH + k];
            const float* wr = Ws + k * 192 + c0;
            #pragma unroll
            for (int g = 0; g < 3; ++g) {
                float4 bv = *(const float4*)(wr + g * 64);
                #pragma unroll
                for (int i = 0; i < 8; ++i) {
                    acc[g][0][i] = fmaf(a[i], bv.x, acc[g][0][i]);
                    acc[g][1][i] = fmaf(a[i], bv.y, acc[g][1][i]);
                    acc[g][2][i] = fmaf(a[i], bv.z, acc[g][2][i]);
                    acc[g][3][i] = fmaf(a[i], bv.w, acc[g][3][i]);
                }
            }
        }
        __syncthreads();   // all reads of sh/Ws done -> safe to write sh in place

        #pragma unroll
        for (int j = 0; j < 4; ++j) {
            float bi = Bs[c0 + j], bg = Bs[64 + c0 + j], bo = Bs[128 + c0 + j];
            #pragma unroll
            for (int i = 0; i < 8; ++i) {
                float iv = acc[0][j][i] + bi;
                float gv = acc[1][j][i] + bg;
                float ov = acc[2][j][i] + bo;
                float cc = hsig(iv) * tanh_fast(gv);
                float hh = hsig(ov) * tanh_fast(cc);
                sh[(m0 + i) * CH + c0 + j] = hh;
            }
        }
        __syncthreads();   // stores visible + Bs safe to overwrite next layer
    }

    // store layer-4 h (== flat, since flat index = w*64 + c and p = b*2048 + w)
    {
        float4* hout = (float4*)(g_h4 + p0 * CH);
        const float4* sh4 = (const float4*)sh;
        #pragma unroll
        for (int i = 0; i < (MT * CH / 4) / 256; ++i)
            hout[tid + i * 256] = sh4[tid + i * 256];
    }
}

// ---------------------------------------------------------------------------
// Kernel B: split-K GEMM  partial[g] = flat[:, kbase:kbase+256] @ D1w[kbase:+256, :]
// M=64(batch), N=64, K-chunk=256. 512 blocks, deterministic.
// ---------------------------------------------------------------------------
__global__ void __launch_bounds__(256) k_dense_split(const float* __restrict__ D1w)
{
    extern __shared__ float sm[];
    float* As  = sm;             // [64][256]
    float* Bsm = sm + 64 * KC;   // [256][64]
    const int tid = threadIdx.x;
    const size_t kbase = (size_t)blockIdx.x * KC;

    for (int i = tid; i < 64 * (KC / 4); i += 256) {
        int b = i >> 6, kq = i & 63;
        ((float4*)As)[i] = *(const float4*)(g_h4 + (size_t)b * FLATK + kbase + (size_t)kq * 4);
    }
    {
        const float4* d1 = (const float4*)(D1w + kbase * 64);
        for (int i = tid; i < KC * 16; i += 256) ((float4*)Bsm)[i] = d1[i];
    }
    __syncthreads();

    const int tx = tid & 15, ty = tid >> 4;
    const int b0 = ty * 4, n0 = tx * 4;
    float acc[4][4] = {};
    #pragma unroll 4
    for (int k = 0; k < KC; ++k) {
        float4 bv = *(const float4*)&Bsm[k * 64 + n0];
        #pragma unroll
        for (int j = 0; j < 4; ++j) {
            float a = As[(b0 + j) * KC + k];
            acc[j][0] = fmaf(a, bv.x, acc[j][0]);
            acc[j][1] = fmaf(a, bv.y, acc[j][1]);
            acc[j][2] = fmaf(a, bv.z, acc[j][2]);
            acc[j][3] = fmaf(a, bv.w, acc[j][3]);
        }
    }
    float* dst = g_part + (size_t)blockIdx.x * 4096;
    #pragma unroll
    for (int j = 0; j < 4; ++j)
        *(float4*)&dst[(b0 + j) * 64 + n0] =
            make_float4(acc[j][0], acc[j][1], acc[j][2], acc[j][3]);
}

// ---------------------------------------------------------------------------
// Kernel C: fixed-order reduce of 512 partials + D1b + relu + D2 GEMV.
// One block per batch row, 256 threads (4 g-slices x 64 n).
// ---------------------------------------------------------------------------
__global__ void k_final(const float* __restrict__ D1b, const float* __restrict__ D2w,
                        const float* __restrict__ D2b, float* __restrict__ out)
{
    __shared__ float sred[256];
    __shared__ float sA[2];
    const int b = blockIdx.x, tid = threadIdx.x;
    const int n = tid & 63, slice = tid >> 6;
    const float* p = g_part + (size_t)slice * 128 * 4096 + (size_t)b * 64 + n;
    float s = 0.f;
    #pragma unroll 8
    for (int g = 0; g < 128; ++g) s += p[(size_t)g * 4096];
    sred[tid] = s;
    __syncthreads();
    if (tid < 64) {
        float v = sred[tid] + sred[tid + 64] + sred[tid + 128] + sred[tid + 192];
        float y = fmaxf(v + D1b[n], 0.f) * D2w[n];
        #pragma unroll
        for (int off = 16; off > 0; off >>= 1)
            y += __shfl_down_sync(0xffffffffu, y, off);
        if ((tid & 31) == 0) sA[tid >> 5] = y;
    }
    __syncthreads();
    if (tid == 0) out[b] = sA[0] + sA[1] + D2b[0];
}

// ---------------------------------------------------------------------------
extern "C" void kernel_launch(void* const* d_in, const int* in_sizes, int n_in,
                              void* d_out, int out_size)
{
    const float* x   = (const float*)d_in[0];
    const float* W1x = (const float*)d_in[1];
    const float* b1  = (const float*)d_in[3];
    const float* W2x = (const float*)d_in[4];
    const float* b2  = (const float*)d_in[6];
    const float* W3x = (const float*)d_in[7];
    const float* b3  = (const float*)d_in[9];
    const float* W4x = (const float*)d_in[10];
    const float* b4  = (const float*)d_in[12];
    const float* D1w = (const float*)d_in[13];
    const float* D1b = (const float*)d_in[14];
    const float* D2w = (const float*)d_in[15];
    const float* D2b = (const float*)d_in[16];

    const int smemA = (MT * CH + CH * 192 + 192) * 4;   // 82688 B
    const int smemB = (64 * KC + KC * 64) * 4;          // 131072 B
    cudaFuncSetAttribute(k_lstm4, cudaFuncAttributeMaxDynamicSharedMemorySize, smemA);
    cudaFuncSetAttribute(k_dense_split, cudaFuncAttributeMaxDynamicSharedMemorySize, smemB);

    // SAME padding over H=1 picks exactly one kernel row: r=4 (kh=10), r=2 (kh=5)
    k_lstm4<<<NBLK_A, 256, smemA>>>(x,
        W1x + 4 * 64 * 256, b1,
        W2x + 2 * 64 * 256, b2,
        W3x + 4 * 64 * 256, b3,
        W4x + 2 * 64 * 256, b4);
    k_dense_split<<<GSPLIT, 256, smemB>>>(D1w);
    k_final<<<BATCH, 256>>>(D1b, D2w, D2b, (float*)d_out);
}

// round 2
// speedup vs baseline: 1.2274x; 1.2274x over previous
#include <cuda_runtime.h>
#include <math.h>

#define BATCH 64
#define WPOS  2048
#define NPOS  (BATCH * WPOS)      // 131072 positions
#define CH    64                  // channels per layer
#define MT    128                 // positions per block (kernel A)
#define NBLK_A (NPOS / MT)        // 1024
#define KC    128                 // K chunk for dense split-K
#define FLATK (WPOS * CH)         // 131072
#define GSPLIT (FLATK / KC)       // 1024

// Scratch (device globals — no allocation allowed)
__device__ __align__(16) float g_h4[(size_t)NPOS * CH];          // 32 MB
__device__ __align__(16) float g_part[(size_t)GSPLIT * 64 * 64]; // 16 MB

typedef unsigned long long u64;

__device__ __forceinline__ u64 pk2(float lo, float hi) {
    u64 r; asm("mov.b64 %0,{%1,%2};" : "=l"(r) : "f"(lo), "f"(hi)); return r;
}
__device__ __forceinline__ void upk2(u64 v, float& lo, float& hi) {
    asm("mov.b64 {%0,%1},%2;" : "=f"(lo), "=f"(hi) : "l"(v));
}
__device__ __forceinline__ u64 ffma2(u64 a, u64 b, u64 c) {
    u64 d; asm("fma.rn.f32x2 %0,%1,%2,%3;" : "=l"(d) : "l"(a), "l"(b), "l"(c)); return d;
}

__device__ __forceinline__ float hsig(float v) {
    return __saturatef(fmaf(v, 0.2f, 0.5f));
}
__device__ __forceinline__ float tanh_fast(float v) {
    float xc = fminf(fmaxf(v, -15.f), 15.f);
    float e = __expf(xc + xc);
    return __fdividef(e - 1.f, e + 1.f);
}

// ---------------------------------------------------------------------------
// Kernel A: fused 4x ConvLSTM layers. Each layer = per-position 64->192 matmul
// (f gate dead: c0==0; Wh dead: h0==0) + gate activations.
// 128 positions/block, 256 threads, tile 8m x 4c x 3g, FMAs packed over c.
// ---------------------------------------------------------------------------
__global__ void __launch_bounds__(256, 2) k_lstm4(
    const float* __restrict__ x,
    const float* __restrict__ W0, const float* __restrict__ B0,
    const float* __restrict__ W1, const float* __restrict__ B1,
    const float* __restrict__ W2, const float* __restrict__ B2,
    const float* __restrict__ W3, const float* __restrict__ B3)
{
    extern __shared__ float sm[];
    float* sh = sm;                  // h buffer [128][64] (in-place across layers)
    float* Ws = sm + MT * CH;        // weights  [64][192]  ([k][gate*64+c], gates i,g,o)
    float* Bs = Ws + CH * 192;       // bias     [192]

    const int tid = threadIdx.x;
    const int tx = tid & 15, ty = tid >> 4;
    const int m0 = ty * 8, c0 = tx * 4;
    const size_t p0 = (size_t)blockIdx.x * MT;

    {   // load input tile (coalesced float4)
        const float4* xin = (const float4*)(x + p0 * CH);
        float4* sh4 = (float4*)sh;
        #pragma unroll
        for (int i = 0; i < (MT * CH / 4) / 256; ++i)
            sh4[tid + i * 256] = xin[tid + i * 256];
    }

    const float* Wl[4] = {W0, W1, W2, W3};
    const float* Bl[4] = {B0, B1, B2, B3};

    #pragma unroll 1
    for (int l = 0; l < 4; ++l) {
        const float* W  = Wl[l];
        const float* Bb = Bl[l];
        for (int i = tid; i < CH * 64; i += 256) {   // float4-indexed [64][256] slice
            int k  = i >> 6;
            int nq = (i & 63) << 2;
            float4 v = ((const float4*)W)[i];
            if (nq < 64)        *(float4*)&Ws[k * 192 + nq]      = v;  // i gate
            else if (nq >= 128) *(float4*)&Ws[k * 192 + nq - 64] = v;  // g, o gates
        }
        if (tid < 192) {
            int gate = tid >> 6, c = tid & 63;
            int gn = (gate == 0) ? c : (gate == 1 ? 128 + c : 192 + c);
            Bs[tid] = Bb[gn];
        }
        __syncthreads();

        // packed accumulators: [gate][c-pair][m], each u64 = 2 f32 (c0+2jp, c0+2jp+1)
        u64 acc[3][2][8];
        #pragma unroll
        for (int g = 0; g < 3; ++g)
            #pragma unroll
            for (int jp = 0; jp < 2; ++jp)
                #pragma unroll
                for (int i = 0; i < 8; ++i) acc[g][jp][i] = 0ull;

        #pragma unroll 1
        for (int k = 0; k < CH; ++k) {
            u64 pa[8];
            #pragma unroll
            for (int i = 0; i < 8; ++i) {
                float a = sh[(m0 + i) * CH + k];
                pa[i] = pk2(a, a);
            }
            const float* wr = Ws + k * 192 + c0;
            #pragma unroll
            for (int g = 0; g < 3; ++g) {
                // LDS.128 -> aligned reg quad -> two b64 operands, no pack movs
                ulonglong2 bw = *(const ulonglong2*)(wr + g * 64);
                #pragma unroll
                for (int i = 0; i < 8; ++i) {
                    acc[g][0][i] = ffma2(pa[i], bw.x, acc[g][0][i]);
                    acc[g][1][i] = ffma2(pa[i], bw.y, acc[g][1][i]);
                }
            }
        }
        __syncthreads();   // reads of sh/Ws done -> safe to overwrite sh

        #pragma unroll
        for (int jp = 0; jp < 2; ++jp) {
            float bi0 = Bs[c0 + 2 * jp],       bi1 = Bs[c0 + 2 * jp + 1];
            float bg0 = Bs[64 + c0 + 2 * jp],  bg1 = Bs[64 + c0 + 2 * jp + 1];
            float bo0 = Bs[128 + c0 + 2 * jp], bo1 = Bs[128 + c0 + 2 * jp + 1];
            #pragma unroll
            for (int i = 0; i < 8; ++i) {
                float iv0, iv1, gv0, gv1, ov0, ov1;
                upk2(acc[0][jp][i], iv0, iv1);
                upk2(acc[1][jp][i], gv0, gv1);
                upk2(acc[2][jp][i], ov0, ov1);
                float cc0 = hsig(iv0 + bi0) * tanh_fast(gv0 + bg0);
                float cc1 = hsig(iv1 + bi1) * tanh_fast(gv1 + bg1);
                float hh0 = hsig(ov0 + bo0) * tanh_fast(cc0);
                float hh1 = hsig(ov1 + bo1) * tanh_fast(cc1);
                sh[(m0 + i) * CH + c0 + 2 * jp]     = hh0;
                sh[(m0 + i) * CH + c0 + 2 * jp + 1] = hh1;
            }
        }
        __syncthreads();
    }

    {   // store layer-4 h (== flat: flat idx = w*64+c, p = b*2048+w)
        float4* hout = (float4*)(g_h4 + p0 * CH);
        const float4* sh4 = (const float4*)sh;
        #pragma unroll
        for (int i = 0; i < (MT * CH / 4) / 256; ++i)
            hout[tid + i * 256] = sh4[tid + i * 256];
    }
}

// ---------------------------------------------------------------------------
// Kernel B: split-K GEMM  partial[g] = flat[:, kb:kb+128] @ D1w[kb:kb+128, :]
// M=64(batch), N=64, K-chunk=128. 1024 blocks, smem 64KB -> 3 blocks/SM.
// ---------------------------------------------------------------------------
__global__ void __launch_bounds__(256) k_dense_split(const float* __restrict__ D1w)
{
    extern __shared__ float sm[];
    float* As  = sm;             // [64][128]
    float* Bsm = sm + 64 * KC;   // [128][64]
    const int tid = threadIdx.x;
    const size_t kbase = (size_t)blockIdx.x * KC;

    for (int i = tid; i < 64 * (KC / 4); i += 256) {
        int b = i / (KC / 4), kq = i % (KC / 4);
        ((float4*)As)[i] = *(const float4*)(g_h4 + (size_t)b * FLATK + kbase + (size_t)kq * 4);
    }
    {
        const float4* d1 = (const float4*)(D1w + kbase * 64);
        for (int i = tid; i < KC * 16; i += 256) ((float4*)Bsm)[i] = d1[i];
    }
    __syncthreads();

    const int tx = tid & 15, ty = tid >> 4;
    const int b0 = ty * 4, n0 = tx * 4;
    u64 acc[4][2] = {};
    #pragma unroll 4
    for (int k = 0; k < KC; ++k) {
        ulonglong2 bw = *(const ulonglong2*)&Bsm[k * 64 + n0];
        #pragma unroll
        for (int j = 0; j < 4; ++j) {
            float a = As[(b0 + j) * KC + k];
            u64 pa = pk2(a, a);
            acc[j][0] = ffma2(pa, bw.x, acc[j][0]);
            acc[j][1] = ffma2(pa, bw.y, acc[j][1]);
        }
    }
    float* dst = g_part + (size_t)blockIdx.x * 4096;
    #pragma unroll
    for (int j = 0; j < 4; ++j) {
        float a0, a1, a2, a3;
        upk2(acc[j][0], a0, a1);
        upk2(acc[j][1], a2, a3);
        *(float4*)&dst[(b0 + j) * 64 + n0] = make_float4(a0, a1, a2, a3);
    }
}

// ---------------------------------------------------------------------------
// Kernel C: fixed-order reduce of 1024 partials + D1b + relu + D2 GEMV.
// ---------------------------------------------------------------------------
__global__ void k_final(const float* __restrict__ D1b, const float* __restrict__ D2w,
                        const float* __restrict__ D2b, float* __restrict__ out)
{
    __shared__ float sred[256];
    __shared__ float sA[2];
    const int b = blockIdx.x, tid = threadIdx.x;
    const int n = tid & 63, slice = tid >> 6;
    const float* p = g_part + (size_t)slice * (GSPLIT / 4) * 4096 + (size_t)b * 64 + n;
    float s = 0.f;
    #pragma unroll 8
    for (int g = 0; g < GSPLIT / 4; ++g) s += p[(size_t)g * 4096];
    sred[tid] = s;
    __syncthreads();
    if (tid < 64) {
        float v = sred[tid] + sred[tid + 64] + sred[tid + 128] + sred[tid + 192];
        float y = fmaxf(v + D1b[n], 0.f) * D2w[n];
        #pragma unroll
        for (int off = 16; off > 0; off >>= 1)
            y += __shfl_down_sync(0xffffffffu, y, off);
        if ((tid & 31) == 0) sA[tid >> 5] = y;
    }
    __syncthreads();
    if (tid == 0) out[b] = sA[0] + sA[1] + D2b[0];
}

// ---------------------------------------------------------------------------
extern "C" void kernel_launch(void* const* d_in, const int* in_sizes, int n_in,
                              void* d_out, int out_size)
{
    const float* x   = (const float*)d_in[0];
    const float* W1x = (const float*)d_in[1];
    const float* b1  = (const float*)d_in[3];
    const float* W2x = (const float*)d_in[4];
    const float* b2  = (const float*)d_in[6];
    const float* W3x = (const float*)d_in[7];
    const float* b3  = (const float*)d_in[9];
    const float* W4x = (const float*)d_in[10];
    const float* b4  = (const float*)d_in[12];
    const float* D1w = (const float*)d_in[13];
    const float* D1b = (const float*)d_in[14];
    const float* D2w = (const float*)d_in[15];
    const float* D2b = (const float*)d_in[16];

    const int smemA = (MT * CH + CH * 192 + 192) * 4;   // 82688 B
    const int smemB = (64 * KC + KC * 64) * 4;          // 65536 B
    cudaFuncSetAttribute(k_lstm4, cudaFuncAttributeMaxDynamicSharedMemorySize, smemA);
    cudaFuncSetAttribute(k_dense_split, cudaFuncAttributeMaxDynamicSharedMemorySize, smemB);

    // SAME padding over H=1 picks exactly one kernel row: r=4 (kh=10), r=2 (kh=5)
    k_lstm4<<<NBLK_A, 256, smemA>>>(x,
        W1x + 4 * 64 * 256, b1,
        W2x + 2 * 64 * 256, b2,
        W3x + 4 * 64 * 256, b3,
        W4x + 2 * 64 * 256, b4);
    k_dense_split<<<GSPLIT, 256, smemB>>>(D1w);
    k_final<<<BATCH, 256>>>(D1b, D2w, D2b, (float*)d_out);
}